// round 15
// baseline (speedup 1.0000x reference)
#include <cuda_runtime.h>
#include <cuda_fp16.h>
#include <cstdint>

// Problem constants
constexpr int B_ = 4;
constexpr int T_ = 2048;
constexpr int C_ = 1024;
constexpr int H_ = 16;
constexpr int HD = 64;
constexpr int BH = B_ * H_;     // 64
constexpr int M_ROWS = B_ * T_; // 8192
constexpr int N_QKV = 3 * C_;   // 3072

constexpr float SCALE = -1.0f / 16.0f; // -1/(2*sqrt(64))

// Device scratch (no cudaMalloc). Device globals only referenced in device code.
__device__ __half g_qh[BH * T_ * HD];   // q fp16 [bh][t][d]
__device__ __half g_kh[BH * T_ * HD];   // k fp16 [bh][t][d]
__device__ __half g_vt[BH * HD * T_];   // v fp16 TRANSPOSED [bh][d][t]
__device__ __half g_yh[M_ROWS * C_];    // attention output, fp16 [m][c]
__device__ __half g_xh[M_ROWS * C_];    // x rounded to fp16 [m][k]
__device__ __half g_wat[N_QKV * C_];    // W_attn^T fp16 [n][k]
__device__ __half g_wpt[C_ * C_];       // W_proj^T fp16 [n][k]
__device__ float g_q2[BH * T_];
__device__ float g_k2[BH * T_];

__device__ __forceinline__ void mma_f16(float& c0, float& c1, float& c2, float& c3,
                                        uint32_t a0, uint32_t a1, uint32_t a2, uint32_t a3,
                                        uint32_t b0, uint32_t b1) {
    asm volatile(
        "mma.sync.aligned.m16n8k16.row.col.f32.f16.f16.f32 "
        "{%0,%1,%2,%3}, {%4,%5,%6,%7}, {%8,%9}, {%0,%1,%2,%3};"
        : "+f"(c0), "+f"(c1), "+f"(c2), "+f"(c3)
        : "r"(a0), "r"(a1), "r"(a2), "r"(a3), "r"(b0), "r"(b1));
}

__device__ __forceinline__ void ldsm_x4(uint32_t& r0, uint32_t& r1,
                                        uint32_t& r2, uint32_t& r3, uint32_t addr) {
    asm volatile("ldmatrix.sync.aligned.m8n8.x4.shared.b16 {%0,%1,%2,%3}, [%4];"
                 : "=r"(r0), "=r"(r1), "=r"(r2), "=r"(r3) : "r"(addr));
}

__device__ __forceinline__ void cp_async16(uint32_t dst, const void* src) {
    asm volatile("cp.async.cg.shared.global [%0], [%1], 16;" :: "r"(dst), "l"(src));
}
__device__ __forceinline__ void cp_commit() {
    asm volatile("cp.async.commit_group;");
}
template <int N>
__device__ __forceinline__ void cp_wait() {
    asm volatile("cp.async.wait_group %0;" :: "n"(N));
}
__device__ __forceinline__ uint32_t smem_u32(const void* p) {
    return (uint32_t)__cvta_generic_to_shared(p);
}
__device__ __forceinline__ uint32_t h2u(half2 h) {
    return *(uint32_t*)&h;
}

// ---------------------------------------------------------------------------
// Prep: round x to fp16; transpose W matrices to N-major fp16.
// ---------------------------------------------------------------------------
__global__ void round_x(const float* __restrict__ x) {
    size_t i = (size_t)blockIdx.x * blockDim.x + threadIdx.x;
    if (i >= (size_t)M_ROWS * C_ / 4) return;
    float4 v = ((const float4*)x)[i];
    ((half2*)g_xh)[i * 2 + 0] = __floats2half2_rn(v.x, v.y);
    ((half2*)g_xh)[i * 2 + 1] = __floats2half2_rn(v.z, v.w);
}

template <int WSEL>
__global__ void transpose_half(const float* __restrict__ in, int K, int N) {
    __half* __restrict__ out = (WSEL == 0) ? g_wat : g_wpt;
    __shared__ float tile[32][33];
    const int n0 = blockIdx.x * 32;
    const int k0 = blockIdx.y * 32;
    const int tx = threadIdx.x;
    const int ty = threadIdx.y;
#pragma unroll
    for (int j = 0; j < 4; j++)
        tile[ty + j * 8][tx] = in[(size_t)(k0 + ty + j * 8) * N + n0 + tx];
    __syncthreads();
#pragma unroll
    for (int j = 0; j < 4; j++)
        out[(size_t)(n0 + ty + j * 8) * K + k0 + tx] =
            __float2half_rn(tile[tx][ty + j * 8]);
}

// ---------------------------------------------------------------------------
// QKV GEMM, occupancy-optimized: tile 128x96, 384 threads = 12 warps (4M x 3N),
// warp 32x32, 3-stage cp.async, BKH=64. Target 85 regs -> 2 CTAs = 24 warps/SM.
// Epilogue scatters fp16 q/k (natural) + v (transposed), part computed
// per-column (96-wide tiles straddle head / qkv-part boundaries).
// ---------------------------------------------------------------------------
constexpr int BKH = 64;
constexpr int HP = 72;
constexpr int QKV_ASZ = 128 * HP;          // A tile halves
constexpr int QKV_BSZ = 96 * HP;           // B tile halves
constexpr int QKV_STG = QKV_ASZ + QKV_BSZ; // per stage
constexpr int QKV_SMEM = 3 * QKV_STG * 2;  // 96768 B

__global__ __launch_bounds__(384, 2) void gemm_qkv(const float* __restrict__ bias) {
    extern __shared__ __half smh[];

    const __half* __restrict__ A = g_xh;
    const __half* __restrict__ Bt = g_wat;

    const int tid = threadIdx.x;
    const int lane = tid & 31;
    const int wid = tid >> 5;
    const int g = lane >> 2;
    const int t4 = lane & 3;
    const int wm = (wid & 3) * 32;   // 4 M-groups
    const int wn = (wid >> 2) * 32;  // 3 N-groups
    const int m0 = blockIdx.y * 128;
    const int n0 = blockIdx.x * 96;
    const int lrow = lane & 15;
    const int lk = (lane >> 4) * 8;

    const int K = C_;
    const int nt = K / BKH; // 16

    auto issue = [&](int stage, int k0) {
        __half* sA = smh + stage * QKV_STG;
        __half* sB = sA + QKV_ASZ;
        // A: 128 rows x 8 chunks = 1024; B: 96 rows x 8 chunks = 768; total 1792.
#pragma unroll
        for (int h = 0; h < 5; h++) {
            int c = tid + h * 384;
            if (h == 4 && c >= 1792) break;
            if (c < 1024) {
                int row = c >> 3, c8 = (c & 7) * 8;
                cp_async16(smem_u32(&sA[row * HP + c8]),
                           &A[(size_t)(m0 + row) * K + k0 + c8]);
            } else {
                int cb = c - 1024;
                int row = cb >> 3, c8 = (cb & 7) * 8;
                cp_async16(smem_u32(&sB[row * HP + c8]),
                           &Bt[(size_t)(n0 + row) * K + k0 + c8]);
            }
        }
        cp_commit();
    };

    float acc[2][4][4] = {};

    issue(0, 0);
    issue(1, BKH);

    for (int i = 0; i < nt; i++) {
        if (i == nt - 1) cp_wait<0>(); else cp_wait<1>();
        __syncthreads();
        if (i + 2 < nt) issue((i + 2) % 3, (i + 2) * BKH);

        const __half* sA = smh + (i % 3) * QKV_STG;
        const __half* sB = sA + QKV_ASZ;

#pragma unroll
        for (int kk = 0; kk < BKH; kk += 16) {
            uint32_t af[2][4];
#pragma unroll
            for (int mi = 0; mi < 2; mi++)
                ldsm_x4(af[mi][0], af[mi][1], af[mi][2], af[mi][3],
                        smem_u32(&sA[(wm + mi * 16 + lrow) * HP + kk + lk]));
            uint32_t bf[4][2];
#pragma unroll
            for (int nj = 0; nj < 2; nj++)
                ldsm_x4(bf[2 * nj][0], bf[2 * nj + 1][0], bf[2 * nj][1], bf[2 * nj + 1][1],
                        smem_u32(&sB[(wn + nj * 16 + lrow) * HP + kk + lk]));
#pragma unroll
            for (int mi = 0; mi < 2; mi++)
#pragma unroll
                for (int ni = 0; ni < 4; ni++)
                    mma_f16(acc[mi][ni][0], acc[mi][ni][1], acc[mi][ni][2], acc[mi][ni][3],
                            af[mi][0], af[mi][1], af[mi][2], af[mi][3],
                            bf[ni][0], bf[ni][1]);
        }
    }

    // Epilogue: per-column part/head decode (tiles straddle boundaries)
#pragma unroll
    for (int mi = 0; mi < 2; mi++) {
#pragma unroll
        for (int ni = 0; ni < 4; ni++) {
            const int r0 = m0 + wm + mi * 16 + g;
            const int r1 = r0 + 8;
            const int n = n0 + wn + ni * 8 + 2 * t4;
            const float bia = bias[n];
            const float bib = bias[n + 1];
            const __half h00 = __float2half_rn(acc[mi][ni][0] + bia);
            const __half h01 = __float2half_rn(acc[mi][ni][1] + bib);
            const __half h10 = __float2half_rn(acc[mi][ni][2] + bia);
            const __half h11 = __float2half_rn(acc[mi][ni][3] + bib);
            const int part = n >> 10;
            const int cc = n & 1023;
            const int h = cc >> 6;
            const int d0 = cc & 63;
#pragma unroll
            for (int e = 0; e < 4; e++) {
                const int m = (e < 2) ? r0 : r1;
                const int dd = d0 + (e & 1);
                const __half hv = (e == 0) ? h00 : (e == 1) ? h01 : (e == 2) ? h10 : h11;
                const int b = m >> 11;
                const int t = m & 2047;
                const int bh = b * H_ + h;
                if (part == 0)
                    g_qh[((size_t)bh * T_ + t) * HD + dd] = hv;
                else if (part == 1)
                    g_kh[((size_t)bh * T_ + t) * HD + dd] = hv;
                else
                    g_vt[((size_t)bh * HD + dd) * T_ + t] = hv;
            }
        }
    }
}

// ---------------------------------------------------------------------------
// Proj GEMM (R14-passing core): C = A(MxK) * B^T([N][K]) + bias, fp32 out.
// 128x128x64 tile, 3-stage cp.async, 8 warps (4M x 2N), warp 32x64, ldmatrix.
// ---------------------------------------------------------------------------
constexpr int HASZ = 128 * HP;
constexpr int HSTG = 2 * HASZ;
constexpr int GEMM_SMEM = 3 * HSTG * 2;  // 110592 B

__global__ __launch_bounds__(256, 2) void gemm_proj(
    const float* __restrict__ bias, float* __restrict__ Cout)
{
    extern __shared__ __half smh[];

    const __half* __restrict__ A = g_yh;
    const __half* __restrict__ Bt = g_wpt;
    const int N = C_, K = C_;

    const int tid = threadIdx.x;
    const int lane = tid & 31;
    const int wid = tid >> 5;
    const int g = lane >> 2;
    const int t4 = lane & 3;
    const int wm = (wid & 3) * 32;
    const int wn = (wid >> 2) * 64;
    const int m0 = blockIdx.y * 128;
    const int n0 = blockIdx.x * 128;
    const int lrow = lane & 15;
    const int lk = (lane >> 4) * 8;

    const int nt = K / BKH;

    auto issue = [&](int stage, int k0) {
        __half* sA = smh + stage * HSTG;
        __half* sB = sA + HASZ;
#pragma unroll
        for (int h = 0; h < 4; h++) {
            int c = tid + h * 256;
            int row = c >> 3, c8 = (c & 7) * 8;
            cp_async16(smem_u32(&sA[row * HP + c8]), &A[(size_t)(m0 + row) * K + k0 + c8]);
            cp_async16(smem_u32(&sB[row * HP + c8]), &Bt[(size_t)(n0 + row) * K + k0 + c8]);
        }
        cp_commit();
    };

    float acc[2][8][4] = {};

    issue(0, 0);
    issue(1, BKH);

    for (int i = 0; i < nt; i++) {
        if (i == nt - 1) cp_wait<0>(); else cp_wait<1>();
        __syncthreads();
        if (i + 2 < nt) issue((i + 2) % 3, (i + 2) * BKH);

        const __half* sA = smh + (i % 3) * HSTG;
        const __half* sB = sA + HASZ;

#pragma unroll
        for (int kk = 0; kk < BKH; kk += 16) {
            uint32_t af[2][4];
#pragma unroll
            for (int mi = 0; mi < 2; mi++)
                ldsm_x4(af[mi][0], af[mi][1], af[mi][2], af[mi][3],
                        smem_u32(&sA[(wm + mi * 16 + lrow) * HP + kk + lk]));
            uint32_t bf[8][2];
#pragma unroll
            for (int nj = 0; nj < 4; nj++)
                ldsm_x4(bf[2 * nj][0], bf[2 * nj + 1][0], bf[2 * nj][1], bf[2 * nj + 1][1],
                        smem_u32(&sB[(wn + nj * 16 + lrow) * HP + kk + lk]));
#pragma unroll
            for (int mi = 0; mi < 2; mi++)
#pragma unroll
                for (int ni = 0; ni < 8; ni++)
                    mma_f16(acc[mi][ni][0], acc[mi][ni][1], acc[mi][ni][2], acc[mi][ni][3],
                            af[mi][0], af[mi][1], af[mi][2], af[mi][3],
                            bf[ni][0], bf[ni][1]);
        }
    }

#pragma unroll
    for (int mi = 0; mi < 2; mi++) {
#pragma unroll
        for (int ni = 0; ni < 8; ni++) {
            const int r0 = m0 + wm + mi * 16 + g;
            const int r1 = r0 + 8;
            const int c0 = n0 + wn + ni * 8 + 2 * t4;
            const float bia = bias[c0];
            const float bib = bias[c0 + 1];
            *(float2*)&Cout[(size_t)r0 * N + c0] =
                make_float2(acc[mi][ni][0] + bia, acc[mi][ni][1] + bib);
            *(float2*)&Cout[(size_t)r1 * N + c0] =
                make_float2(acc[mi][ni][2] + bia, acc[mi][ni][3] + bib);
        }
    }
}

// ---------------------------------------------------------------------------
// Row squared norms of q and k from the stored fp16 values
// ---------------------------------------------------------------------------
__global__ void q2k2_kernel() {
    const int idx = blockIdx.x * blockDim.x + threadIdx.x;
    if (idx >= BH * T_) return;
    const half2* q = (const half2*)(g_qh + (size_t)idx * HD);
    const half2* k = (const half2*)(g_kh + (size_t)idx * HD);
    float sq = 0.0f, sk = 0.0f;
#pragma unroll
    for (int i = 0; i < HD / 2; i++) {
        float2 a = __half22float2(q[i]);
        sq += a.x * a.x + a.y * a.y;
        float2 b = __half22float2(k[i]);
        sk += b.x * b.x + b.y * b.y;
    }
    g_q2[idx] = sq;
    g_k2[idx] = sk;
}

// ---------------------------------------------------------------------------
// Streaming causal Gaussian attention (R14-passing): register-resident S,
// 8 warps x 16-row bands, 3-stage KV ring with 2 prefetches in flight.
// ---------------------------------------------------------------------------
constexpr int QP = 72;
constexpr int Q_OFF = 0;
constexpr int K_OFF = 128 * QP;
constexpr int V_OFF = K_OFF + 3 * 64 * QP;
constexpr int ATTN_SMEM = (V_OFF + 3 * 64 * QP) * 2; // 73728 B

__global__ __launch_bounds__(256, 2) void attn_f16() {
    extern __shared__ __half smh[];
    __half* Qs = smh + Q_OFF;

    const int bh = blockIdx.y;
    const int qt = (int)gridDim.x - 1 - (int)blockIdx.x; // longest blocks first
    const int q0 = qt * 128;
    const int tid = threadIdx.x;
    const int lane = tid & 31;
    const int wid = tid >> 5;
    const int g = lane >> 2;
    const int t4 = lane & 3;
    const int wm = wid * 16;
    const int lrow = lane & 15;
    const int lk = (lane >> 4) * 8;

    const __half* __restrict__ qp = g_qh + (size_t)bh * T_ * HD;
    const __half* __restrict__ kp = g_kh + (size_t)bh * T_ * HD;
    const __half* __restrict__ vtp = g_vt + (size_t)bh * HD * T_;

    const int ntile = 2 * qt + 2;

    auto issueKV = [&](int stage, int k0) {
        __half* Ks = smh + K_OFF + stage * 64 * QP;
        __half* Vs = smh + V_OFF + stage * 64 * QP;
#pragma unroll
        for (int h2 = 0; h2 < 2; h2++) {
            int c = tid + h2 * 256;
            int row = c >> 3, cc = (c & 7) * 8;
            cp_async16(smem_u32(&Ks[row * QP + cc]), &kp[(size_t)(k0 + row) * HD + cc]);
            cp_async16(smem_u32(&Vs[row * QP + cc]), &vtp[(size_t)row * T_ + k0 + cc]);
        }
        cp_commit();
    };

    {
#pragma unroll
        for (int h2 = 0; h2 < 4; h2++) {
            int c = tid + h2 * 256;
            int row = c >> 3, cc = (c & 7) * 8;
            cp_async16(smem_u32(&Qs[row * QP + cc]), &qp[(size_t)(q0 + row) * HD + cc]);
        }
        issueKV(0, 0);
        issueKV(1, 64);
    }

    const float q2a = g_q2[bh * T_ + q0 + wm + g];
    const float q2b = g_q2[bh * T_ + q0 + wm + g + 8];
    const int tq0 = q0 + wm + g;
    const int tq1 = tq0 + 8;

    float yacc[8][4] = {};

    for (int jt = 0; jt < ntile; jt++) {
        const int st = jt % 3;
        const int k0 = jt * 64;
        if (jt == ntile - 1) cp_wait<0>(); else cp_wait<1>();
        __syncthreads();
        if (jt + 2 < ntile) issueKV((jt + 2) % 3, (jt + 2) * 64);

        const bool full_mask = (k0 > q0 + wm + 15);
        if (full_mask) continue;

        const __half* Ks = smh + K_OFF + st * 64 * QP;
        const __half* Vs = smh + V_OFF + st * 64 * QP;

        float sacc[8][4] = {};
#pragma unroll
        for (int kk = 0; kk < 64; kk += 16) {
            uint32_t a0, a1, a2, a3;
            ldsm_x4(a0, a1, a2, a3, smem_u32(&Qs[(wm + lrow) * QP + kk + lk]));
            uint32_t bf[8][2];
#pragma unroll
            for (int nj = 0; nj < 4; nj++)
                ldsm_x4(bf[2 * nj][0], bf[2 * nj + 1][0], bf[2 * nj][1], bf[2 * nj + 1][1],
                        smem_u32(&Ks[(nj * 16 + lrow) * QP + kk + lk]));
#pragma unroll
            for (int j = 0; j < 8; j++)
                mma_f16(sacc[j][0], sacc[j][1], sacc[j][2], sacc[j][3],
                        a0, a1, a2, a3, bf[j][0], bf[j][1]);
        }

        uint32_t sa[4][4];
#pragma unroll
        for (int j = 0; j < 8; j++) {
            const int c0l = j * 8 + 2 * t4;
            const int tk0 = k0 + c0l;
            const int tk1 = tk0 + 1;
            const float2 k2 = *(const float2*)&g_k2[bh * T_ + tk0];
            float e00 = __expf((q2a + k2.x - 2.0f * sacc[j][0]) * SCALE);
            float e01 = __expf((q2a + k2.y - 2.0f * sacc[j][1]) * SCALE);
            float e10 = __expf((q2b + k2.x - 2.0f * sacc[j][2]) * SCALE);
            float e11 = __expf((q2b + k2.y - 2.0f * sacc[j][3]) * SCALE);
            if (tk0 > tq0) e00 = 0.0f;
            if (tk1 > tq0) e01 = 0.0f;
            if (tk0 > tq1) e10 = 0.0f;
            if (tk1 > tq1) e11 = 0.0f;
            sa[j >> 1][(j & 1) * 2 + 0] = h2u(__floats2half2_rn(e00, e01));
            sa[j >> 1][(j & 1) * 2 + 1] = h2u(__floats2half2_rn(e10, e11));
        }

#pragma unroll
        for (int s = 0; s < 4; s++) {
            uint32_t bf[8][2];
#pragma unroll
            for (int nj = 0; nj < 4; nj++)
                ldsm_x4(bf[2 * nj][0], bf[2 * nj + 1][0], bf[2 * nj][1], bf[2 * nj + 1][1],
                        smem_u32(&Vs[(nj * 16 + lrow) * QP + 16 * s + lk]));
#pragma unroll
            for (int ni = 0; ni < 8; ni++)
                mma_f16(yacc[ni][0], yacc[ni][1], yacc[ni][2], yacc[ni][3],
                        sa[s][0], sa[s][1], sa[s][2], sa[s][3],
                        bf[ni][0], bf[ni][1]);
        }
    }

    const int b = bh >> 4;
    const int h = bh & 15;
#pragma unroll
    for (int ni = 0; ni < 8; ni++) {
        const int d = ni * 8 + 2 * t4;
        *(half2*)&g_yh[((size_t)(b * T_ + tq0)) * C_ + h * HD + d] =
            __floats2half2_rn(yacc[ni][0], yacc[ni][1]);
        *(half2*)&g_yh[((size_t)(b * T_ + tq1)) * C_ + h * HD + d] =
            __floats2half2_rn(yacc[ni][2], yacc[ni][3]);
    }
}

// ---------------------------------------------------------------------------
extern "C" void kernel_launch(void* const* d_in, const int* in_sizes, int n_in,
                              void* d_out, int out_size) {
    (void)in_sizes; (void)n_in; (void)out_size;
    const float* x      = (const float*)d_in[0];
    const float* W_attn = (const float*)d_in[1];
    const float* b_attn = (const float*)d_in[2];
    const float* W_proj = (const float*)d_in[3];
    const float* b_proj = (const float*)d_in[4];
    float* out = (float*)d_out;

    cudaFuncSetAttribute(gemm_qkv, cudaFuncAttributeMaxDynamicSharedMemorySize, QKV_SMEM);
    cudaFuncSetAttribute(gemm_proj, cudaFuncAttributeMaxDynamicSharedMemorySize, GEMM_SMEM);
    cudaFuncSetAttribute(attn_f16, cudaFuncAttributeMaxDynamicSharedMemorySize, ATTN_SMEM);

    round_x<<<(M_ROWS * C_ / 4 + 255) / 256, 256>>>(x);
    transpose_half<0><<<dim3(N_QKV / 32, C_ / 32), dim3(32, 8)>>>(W_attn, C_, N_QKV);
    transpose_half<1><<<dim3(C_ / 32, C_ / 32), dim3(32, 8)>>>(W_proj, C_, C_);

    gemm_qkv<<<dim3(N_QKV / 96, M_ROWS / 128), 384, QKV_SMEM>>>(b_attn);

    q2k2_kernel<<<(BH * T_ + 255) / 256, 256>>>();

    attn_f16<<<dim3(T_ / 128, BH), 256, ATTN_SMEM>>>();

    gemm_proj<<<dim3(C_ / 128, M_ROWS / 128), 256, GEMM_SMEM>>>(b_proj, out);
}

// round 16
// speedup vs baseline: 1.7402x; 1.7402x over previous
#include <cuda_runtime.h>
#include <cuda_fp16.h>
#include <cstdint>

// Problem constants
constexpr int B_ = 4;
constexpr int T_ = 2048;
constexpr int C_ = 1024;
constexpr int H_ = 16;
constexpr int HD = 64;
constexpr int BH = B_ * H_;     // 64
constexpr int M_ROWS = B_ * T_; // 8192
constexpr int N_QKV = 3 * C_;   // 3072

constexpr float SCALE = -1.0f / 16.0f; // -1/(2*sqrt(64))

// Device scratch (no cudaMalloc). Device globals only referenced in device code.
__device__ __half g_qh[BH * T_ * HD];   // q fp16 [bh][t][d]
__device__ __half g_kh[BH * T_ * HD];   // k fp16 [bh][t][d]
__device__ __half g_vt[BH * HD * T_];   // v fp16 TRANSPOSED [bh][d][t]
__device__ __half g_yh[M_ROWS * C_];    // attention output, fp16 [m][c]
__device__ __half g_xh[M_ROWS * C_];    // x rounded to fp16 [m][k]
__device__ __half g_wat[N_QKV * C_];    // W_attn^T fp16 [n][k]
__device__ __half g_wpt[C_ * C_];       // W_proj^T fp16 [n][k]
__device__ float g_q2[BH * T_];
__device__ float g_k2[BH * T_];

__device__ __forceinline__ void mma_f16(float& c0, float& c1, float& c2, float& c3,
                                        uint32_t a0, uint32_t a1, uint32_t a2, uint32_t a3,
                                        uint32_t b0, uint32_t b1) {
    asm volatile(
        "mma.sync.aligned.m16n8k16.row.col.f32.f16.f16.f32 "
        "{%0,%1,%2,%3}, {%4,%5,%6,%7}, {%8,%9}, {%0,%1,%2,%3};"
        : "+f"(c0), "+f"(c1), "+f"(c2), "+f"(c3)
        : "r"(a0), "r"(a1), "r"(a2), "r"(a3), "r"(b0), "r"(b1));
}

__device__ __forceinline__ void ldsm_x4(uint32_t& r0, uint32_t& r1,
                                        uint32_t& r2, uint32_t& r3, uint32_t addr) {
    asm volatile("ldmatrix.sync.aligned.m8n8.x4.shared.b16 {%0,%1,%2,%3}, [%4];"
                 : "=r"(r0), "=r"(r1), "=r"(r2), "=r"(r3) : "r"(addr));
}

__device__ __forceinline__ void cp_async16(uint32_t dst, const void* src) {
    asm volatile("cp.async.cg.shared.global [%0], [%1], 16;" :: "r"(dst), "l"(src));
}
__device__ __forceinline__ void cp_commit() {
    asm volatile("cp.async.commit_group;");
}
template <int N>
__device__ __forceinline__ void cp_wait() {
    asm volatile("cp.async.wait_group %0;" :: "n"(N));
}
__device__ __forceinline__ uint32_t smem_u32(const void* p) {
    return (uint32_t)__cvta_generic_to_shared(p);
}
__device__ __forceinline__ uint32_t h2u(half2 h) {
    return *(uint32_t*)&h;
}

// ---------------------------------------------------------------------------
// Prep: round x to fp16; transpose W matrices to N-major fp16.
// ---------------------------------------------------------------------------
__global__ void round_x(const float* __restrict__ x) {
    size_t i = (size_t)blockIdx.x * blockDim.x + threadIdx.x;
    if (i >= (size_t)M_ROWS * C_ / 4) return;
    float4 v = ((const float4*)x)[i];
    ((half2*)g_xh)[i * 2 + 0] = __floats2half2_rn(v.x, v.y);
    ((half2*)g_xh)[i * 2 + 1] = __floats2half2_rn(v.z, v.w);
}

template <int WSEL>
__global__ void transpose_half(const float* __restrict__ in, int K, int N) {
    __half* __restrict__ out = (WSEL == 0) ? g_wat : g_wpt;
    __shared__ float tile[32][33];
    const int n0 = blockIdx.x * 32;
    const int k0 = blockIdx.y * 32;
    const int tx = threadIdx.x;
    const int ty = threadIdx.y;
#pragma unroll
    for (int j = 0; j < 4; j++)
        tile[ty + j * 8][tx] = in[(size_t)(k0 + ty + j * 8) * N + n0 + tx];
    __syncthreads();
#pragma unroll
    for (int j = 0; j < 4; j++)
        out[(size_t)(n0 + ty + j * 8) * K + k0 + tx] =
            __float2half_rn(tile[tx][ty + j * 8]);
}

// ---------------------------------------------------------------------------
// Dense fp16 GEMM (R14-passing core): C = A(MxK) * B^T([N][K]) + bias, fp32 acc.
// 128x128x64 tile, 3-stage cp.async, 8 warps (4M x 2N), warp 32x64, ldmatrix.
// MODE 0: fused per-row |q|^2/|k|^2 + vectorized half2 stores for q/k.
// ---------------------------------------------------------------------------
constexpr int BKH = 64;
constexpr int HP = 72;
constexpr int HASZ = 128 * HP;
constexpr int HSTG = 2 * HASZ;
constexpr int GEMM_SMEM = 3 * HSTG * 2;  // 110592 B

template <int MODE>
__global__ __launch_bounds__(256, 2) void gemm_f16(
    const float* __restrict__ bias, float* __restrict__ Cout,
    int M, int N, int K)
{
    extern __shared__ __half smh[];

    const __half* __restrict__ A = (MODE == 0) ? g_xh : g_yh;
    const __half* __restrict__ Bt = (MODE == 0) ? g_wat : g_wpt;

    const int tid = threadIdx.x;
    const int lane = tid & 31;
    const int wid = tid >> 5;
    const int g = lane >> 2;
    const int t4 = lane & 3;
    const int wm = (wid & 3) * 32;
    const int wn = (wid >> 2) * 64;
    const int m0 = blockIdx.y * 128;
    const int n0 = blockIdx.x * 128;
    const int lrow = lane & 15;
    const int lk = (lane >> 4) * 8;

    const int nt = K / BKH;

    auto issue = [&](int stage, int k0) {
        __half* sA = smh + stage * HSTG;
        __half* sB = sA + HASZ;
#pragma unroll
        for (int h = 0; h < 4; h++) {
            int c = tid + h * 256;
            int row = c >> 3, c8 = (c & 7) * 8;
            cp_async16(smem_u32(&sA[row * HP + c8]), &A[(size_t)(m0 + row) * K + k0 + c8]);
            cp_async16(smem_u32(&sB[row * HP + c8]), &Bt[(size_t)(n0 + row) * K + k0 + c8]);
        }
        cp_commit();
    };

    float acc[2][8][4] = {};

    issue(0, 0);
    issue(1, BKH);

    for (int i = 0; i < nt; i++) {
        // Outstanding before wait: {i, i+1} for i<=nt-2, only {i} at tail.
        if (i == nt - 1) cp_wait<0>(); else cp_wait<1>();
        __syncthreads();
        if (i + 2 < nt) issue((i + 2) % 3, (i + 2) * BKH);

        const __half* sA = smh + (i % 3) * HSTG;
        const __half* sB = sA + HASZ;

#pragma unroll
        for (int kk = 0; kk < BKH; kk += 16) {
            uint32_t af[2][4];
#pragma unroll
            for (int mi = 0; mi < 2; mi++)
                ldsm_x4(af[mi][0], af[mi][1], af[mi][2], af[mi][3],
                        smem_u32(&sA[(wm + mi * 16 + lrow) * HP + kk + lk]));
            uint32_t bf[8][2];
#pragma unroll
            for (int nj = 0; nj < 4; nj++)
                ldsm_x4(bf[2 * nj][0], bf[2 * nj + 1][0], bf[2 * nj][1], bf[2 * nj + 1][1],
                        smem_u32(&sB[(wn + nj * 16 + lrow) * HP + kk + lk]));
#pragma unroll
            for (int mi = 0; mi < 2; mi++)
#pragma unroll
                for (int ni = 0; ni < 8; ni++)
                    mma_f16(acc[mi][ni][0], acc[mi][ni][1], acc[mi][ni][2], acc[mi][ni][3],
                            af[mi][0], af[mi][1], af[mi][2], af[mi][3],
                            bf[ni][0], bf[ni][1]);
        }
    }

    // Epilogue (+ fused row-norm reduction for q/k in MODE 0)
    float sq0[2] = {0.0f, 0.0f};
    float sq1[2] = {0.0f, 0.0f};
    const int part = (n0 + wn) >> 10; // constant per warp (64-col head block)
    const int hh = ((n0 + wn) & 1023) >> 6; // head, constant per warp

#pragma unroll
    for (int mi = 0; mi < 2; mi++) {
#pragma unroll
        for (int ni = 0; ni < 8; ni++) {
            const int r0 = m0 + wm + mi * 16 + g;
            const int r1 = r0 + 8;
            const int c0 = n0 + wn + ni * 8 + 2 * t4;
            const float bia = bias[c0];
            const float bib = bias[c0 + 1];
            float v00 = acc[mi][ni][0] + bia;
            float v01 = acc[mi][ni][1] + bib;
            float v10 = acc[mi][ni][2] + bia;
            float v11 = acc[mi][ni][3] + bib;
            if (MODE == 0) {
                const half2 p0 = __floats2half2_rn(v00, v01);
                const half2 p1 = __floats2half2_rn(v10, v11);
                const int d0 = ni * 8 + 2 * t4; // within-head dim (64-aligned warp block)
                const int b0i = r0 >> 11, t0i = r0 & 2047;
                const int b1i = r1 >> 11, t1i = r1 & 2047;
                if (part < 2) {
                    const float2 f0 = __half22float2(p0);
                    const float2 f1 = __half22float2(p1);
                    sq0[mi] += f0.x * f0.x + f0.y * f0.y;
                    sq1[mi] += f1.x * f1.x + f1.y * f1.y;
                    __half* dst = (part == 0) ? g_qh : g_kh;
                    *(half2*)&dst[((size_t)(b0i * H_ + hh) * T_ + t0i) * HD + d0] = p0;
                    *(half2*)&dst[((size_t)(b1i * H_ + hh) * T_ + t1i) * HD + d0] = p1;
                } else {
                    // v: transposed layout, scalar stores
                    g_vt[((size_t)(b0i * H_ + hh) * HD + d0) * T_ + t0i] = __low2half(p0);
                    g_vt[((size_t)(b0i * H_ + hh) * HD + d0 + 1) * T_ + t0i] = __high2half(p0);
                    g_vt[((size_t)(b1i * H_ + hh) * HD + d0) * T_ + t1i] = __low2half(p1);
                    g_vt[((size_t)(b1i * H_ + hh) * HD + d0 + 1) * T_ + t1i] = __high2half(p1);
                }
            } else {
                *(float2*)&Cout[(size_t)r0 * N + c0] = make_float2(v00, v01);
                *(float2*)&Cout[(size_t)r1 * N + c0] = make_float2(v10, v11);
            }
        }
    }

    if (MODE == 0 && part < 2) {
        // quad reduce over t4 (lanes 4g..4g+3)
#pragma unroll
        for (int mi = 0; mi < 2; mi++) {
            float s0 = sq0[mi], s1 = sq1[mi];
            s0 += __shfl_xor_sync(0xffffffffu, s0, 1);
            s0 += __shfl_xor_sync(0xffffffffu, s0, 2);
            s1 += __shfl_xor_sync(0xffffffffu, s1, 1);
            s1 += __shfl_xor_sync(0xffffffffu, s1, 2);
            if (t4 == 0) {
                float* dst = (part == 0) ? g_q2 : g_k2;
                const int m0r = m0 + wm + mi * 16 + g;
                {
                    const int b = m0r >> 11, t = m0r & 2047;
                    dst[(b * H_ + hh) * T_ + t] = s0;
                }
                {
                    const int m1r = m0r + 8;
                    const int b = m1r >> 11, t = m1r & 2047;
                    dst[(b * H_ + hh) * T_ + t] = s1;
                }
            }
        }
    }
}

// ---------------------------------------------------------------------------
// Streaming causal Gaussian attention (R14-passing core): register-resident S,
// 8 warps x 16-row bands, 3-stage KV ring (2 prefetches in flight).
// NEW: k2 staged through smem via cp.async (rides the KV commit group).
// ---------------------------------------------------------------------------
constexpr int QP = 72;
constexpr int Q_OFF = 0;
constexpr int K_OFF = 128 * QP;
constexpr int V_OFF = K_OFF + 3 * 64 * QP;
constexpr int K2_OFF_H = V_OFF + 3 * 64 * QP;        // in halves; float area
constexpr int ATTN_SMEM = K2_OFF_H * 2 + 3 * 64 * 4; // 73728 + 768 B

__global__ __launch_bounds__(256, 2) void attn_f16() {
    extern __shared__ __half smh[];
    __half* Qs = smh + Q_OFF;
    float* k2base = (float*)(smh + K2_OFF_H);

    const int bh = blockIdx.y;
    const int qt = (int)gridDim.x - 1 - (int)blockIdx.x; // longest blocks first
    const int q0 = qt * 128;
    const int tid = threadIdx.x;
    const int lane = tid & 31;
    const int wid = tid >> 5;
    const int g = lane >> 2;
    const int t4 = lane & 3;
    const int wm = wid * 16;
    const int lrow = lane & 15;
    const int lk = (lane >> 4) * 8;

    const __half* __restrict__ qp = g_qh + (size_t)bh * T_ * HD;
    const __half* __restrict__ kp = g_kh + (size_t)bh * T_ * HD;
    const __half* __restrict__ vtp = g_vt + (size_t)bh * HD * T_;

    const int ntile = 2 * qt + 2;

    auto issueKV = [&](int stage, int k0) {
        __half* Ks = smh + K_OFF + stage * 64 * QP;
        __half* Vs = smh + V_OFF + stage * 64 * QP;
#pragma unroll
        for (int h2 = 0; h2 < 2; h2++) {
            int c = tid + h2 * 256;
            int row = c >> 3, cc = (c & 7) * 8;
            cp_async16(smem_u32(&Ks[row * QP + cc]), &kp[(size_t)(k0 + row) * HD + cc]);
            cp_async16(smem_u32(&Vs[row * QP + cc]), &vtp[(size_t)row * T_ + k0 + cc]);
        }
        if (tid < 16)
            cp_async16(smem_u32(&k2base[stage * 64 + tid * 4]),
                       &g_k2[bh * T_ + k0 + tid * 4]);
        cp_commit();
    };

    {
#pragma unroll
        for (int h2 = 0; h2 < 4; h2++) {
            int c = tid + h2 * 256;
            int row = c >> 3, cc = (c & 7) * 8;
            cp_async16(smem_u32(&Qs[row * QP + cc]), &qp[(size_t)(q0 + row) * HD + cc]);
        }
        issueKV(0, 0);
        issueKV(1, 64);
    }

    const float q2a = g_q2[bh * T_ + q0 + wm + g];
    const float q2b = g_q2[bh * T_ + q0 + wm + g + 8];
    const int tq0 = q0 + wm + g;
    const int tq1 = tq0 + 8;

    float yacc[8][4] = {};

    for (int jt = 0; jt < ntile; jt++) {
        const int st = jt % 3;
        const int k0 = jt * 64;
        // Outstanding before wait: {jt, jt+1} for jt<=ntile-2, only {jt} at tail.
        if (jt == ntile - 1) cp_wait<0>(); else cp_wait<1>();
        __syncthreads(); // all warps done with tile jt-1 (stage (jt+2)%3)
        if (jt + 2 < ntile) issueKV((jt + 2) % 3, (jt + 2) * 64);

        const bool full_mask = (k0 > q0 + wm + 15);
        if (full_mask) continue;

        const __half* Ks = smh + K_OFF + st * 64 * QP;
        const __half* Vs = smh + V_OFF + st * 64 * QP;
        const float* k2s = k2base + st * 64;

        // S = Q.K^T  (warp m16 x n64)
        float sacc[8][4] = {};
#pragma unroll
        for (int kk = 0; kk < 64; kk += 16) {
            uint32_t a0, a1, a2, a3;
            ldsm_x4(a0, a1, a2, a3, smem_u32(&Qs[(wm + lrow) * QP + kk + lk]));
            uint32_t bf[8][2];
#pragma unroll
            for (int nj = 0; nj < 4; nj++)
                ldsm_x4(bf[2 * nj][0], bf[2 * nj + 1][0], bf[2 * nj][1], bf[2 * nj + 1][1],
                        smem_u32(&Ks[(nj * 16 + lrow) * QP + kk + lk]));
#pragma unroll
            for (int j = 0; j < 8; j++)
                mma_f16(sacc[j][0], sacc[j][1], sacc[j][2], sacc[j][3],
                        a0, a1, a2, a3, bf[j][0], bf[j][1]);
        }

        // exp + causal mask -> pack directly into SV A-fragments (registers)
        uint32_t sa[4][4];
#pragma unroll
        for (int j = 0; j < 8; j++) {
            const int c0l = j * 8 + 2 * t4;
            const int tk0 = k0 + c0l;
            const int tk1 = tk0 + 1;
            const float2 k2 = *(const float2*)&k2s[c0l];
            float e00 = __expf((q2a + k2.x - 2.0f * sacc[j][0]) * SCALE);
            float e01 = __expf((q2a + k2.y - 2.0f * sacc[j][1]) * SCALE);
            float e10 = __expf((q2b + k2.x - 2.0f * sacc[j][2]) * SCALE);
            float e11 = __expf((q2b + k2.y - 2.0f * sacc[j][3]) * SCALE);
            if (tk0 > tq0) e00 = 0.0f;
            if (tk1 > tq0) e01 = 0.0f;
            if (tk0 > tq1) e10 = 0.0f;
            if (tk1 > tq1) e11 = 0.0f;
            sa[j >> 1][(j & 1) * 2 + 0] = h2u(__floats2half2_rn(e00, e01));
            sa[j >> 1][(j & 1) * 2 + 1] = h2u(__floats2half2_rn(e10, e11));
        }

        // Y += S @ V  (A = register S, B = V^T fragments; k = token)
#pragma unroll
        for (int s = 0; s < 4; s++) {
            uint32_t bf[8][2];
#pragma unroll
            for (int nj = 0; nj < 4; nj++)
                ldsm_x4(bf[2 * nj][0], bf[2 * nj + 1][0], bf[2 * nj][1], bf[2 * nj + 1][1],
                        smem_u32(&Vs[(nj * 16 + lrow) * QP + 16 * s + lk]));
#pragma unroll
            for (int ni = 0; ni < 8; ni++)
                mma_f16(yacc[ni][0], yacc[ni][1], yacc[ni][2], yacc[ni][3],
                        sa[s][0], sa[s][1], sa[s][2], sa[s][3],
                        bf[ni][0], bf[ni][1]);
        }
    }

    // Write Y as fp16 to (B,T,C)
    const int b = bh >> 4;
    const int h = bh & 15;
#pragma unroll
    for (int ni = 0; ni < 8; ni++) {
        const int d = ni * 8 + 2 * t4;
        *(half2*)&g_yh[((size_t)(b * T_ + tq0)) * C_ + h * HD + d] =
            __floats2half2_rn(yacc[ni][0], yacc[ni][1]);
        *(half2*)&g_yh[((size_t)(b * T_ + tq1)) * C_ + h * HD + d] =
            __floats2half2_rn(yacc[ni][2], yacc[ni][3]);
    }
}

// ---------------------------------------------------------------------------
extern "C" void kernel_launch(void* const* d_in, const int* in_sizes, int n_in,
                              void* d_out, int out_size) {
    (void)in_sizes; (void)n_in; (void)out_size;
    const float* x      = (const float*)d_in[0];
    const float* W_attn = (const float*)d_in[1];
    const float* b_attn = (const float*)d_in[2];
    const float* W_proj = (const float*)d_in[3];
    const float* b_proj = (const float*)d_in[4];
    float* out = (float*)d_out;

    cudaFuncSetAttribute(gemm_f16<0>, cudaFuncAttributeMaxDynamicSharedMemorySize, GEMM_SMEM);
    cudaFuncSetAttribute(gemm_f16<1>, cudaFuncAttributeMaxDynamicSharedMemorySize, GEMM_SMEM);
    cudaFuncSetAttribute(attn_f16, cudaFuncAttributeMaxDynamicSharedMemorySize, ATTN_SMEM);

    round_x<<<(M_ROWS * C_ / 4 + 255) / 256, 256>>>(x);
    transpose_half<0><<<dim3(N_QKV / 32, C_ / 32), dim3(32, 8)>>>(W_attn, C_, N_QKV);
    transpose_half<1><<<dim3(C_ / 32, C_ / 32), dim3(32, 8)>>>(W_proj, C_, C_);

    dim3 g1(N_QKV / 128, M_ROWS / 128);
    gemm_f16<0><<<g1, 256, GEMM_SMEM>>>(b_attn, nullptr, M_ROWS, N_QKV, C_);

    attn_f16<<<dim3(T_ / 128, BH), 256, ATTN_SMEM>>>();

    dim3 g2(C_ / 128, M_ROWS / 128);
    gemm_f16<1><<<g2, 256, GEMM_SMEM>>>(b_proj, out, M_ROWS, C_, C_);
}

// round 17
// speedup vs baseline: 1.7663x; 1.0150x over previous
#include <cuda_runtime.h>
#include <cuda_fp16.h>
#include <cstdint>

// Problem constants
constexpr int B_ = 4;
constexpr int T_ = 2048;
constexpr int C_ = 1024;
constexpr int H_ = 16;
constexpr int HD = 64;
constexpr int BH = B_ * H_;     // 64
constexpr int M_ROWS = B_ * T_; // 8192
constexpr int N_QKV = 3 * C_;   // 3072

constexpr float SCALE = -1.0f / 16.0f; // -1/(2*sqrt(64))

// Device scratch (no cudaMalloc). Device globals only referenced in device code.
__device__ __half g_qh[BH * T_ * HD];   // q fp16 [bh][t][d]
__device__ __half g_kh[BH * T_ * HD];   // k fp16 [bh][t][d]
__device__ __half g_vt[BH * HD * T_];   // v fp16 TRANSPOSED [bh][d][t]
__device__ __half g_yh[M_ROWS * C_];    // attention output, fp16 [m][c]
__device__ __half g_xh[M_ROWS * C_];    // x rounded to fp16 [m][k]
__device__ __half g_wat[N_QKV * C_];    // W_attn^T fp16 [n][k]
__device__ __half g_wpt[C_ * C_];       // W_proj^T fp16 [n][k]
__device__ float g_q2[BH * T_];
__device__ float g_k2[BH * T_];

__device__ __forceinline__ void mma_f16(float& c0, float& c1, float& c2, float& c3,
                                        uint32_t a0, uint32_t a1, uint32_t a2, uint32_t a3,
                                        uint32_t b0, uint32_t b1) {
    asm volatile(
        "mma.sync.aligned.m16n8k16.row.col.f32.f16.f16.f32 "
        "{%0,%1,%2,%3}, {%4,%5,%6,%7}, {%8,%9}, {%0,%1,%2,%3};"
        : "+f"(c0), "+f"(c1), "+f"(c2), "+f"(c3)
        : "r"(a0), "r"(a1), "r"(a2), "r"(a3), "r"(b0), "r"(b1));
}

__device__ __forceinline__ void ldsm_x4(uint32_t& r0, uint32_t& r1,
                                        uint32_t& r2, uint32_t& r3, uint32_t addr) {
    asm volatile("ldmatrix.sync.aligned.m8n8.x4.shared.b16 {%0,%1,%2,%3}, [%4];"
                 : "=r"(r0), "=r"(r1), "=r"(r2), "=r"(r3) : "r"(addr));
}

__device__ __forceinline__ void cp_async16(uint32_t dst, const void* src) {
    asm volatile("cp.async.cg.shared.global [%0], [%1], 16;" :: "r"(dst), "l"(src));
}
__device__ __forceinline__ void cp_commit() {
    asm volatile("cp.async.commit_group;");
}
template <int N>
__device__ __forceinline__ void cp_wait() {
    asm volatile("cp.async.wait_group %0;" :: "n"(N));
}
__device__ __forceinline__ uint32_t smem_u32(const void* p) {
    return (uint32_t)__cvta_generic_to_shared(p);
}
__device__ __forceinline__ uint32_t h2u(half2 h) {
    return *(uint32_t*)&h;
}

// ---------------------------------------------------------------------------
// Fused prep: one launch. Blocks [0, NBX): round x to fp16.
// Blocks [NBX, NBX+NBWA): transpose W_attn tile. Then W_proj tiles.
// ---------------------------------------------------------------------------
constexpr int NBX = (M_ROWS * C_ / 4) / 256;          // 8192
constexpr int NBWA = (N_QKV / 32) * (C_ / 32);        // 3072
constexpr int NBWP = (C_ / 32) * (C_ / 32);           // 1024
constexpr int WA_NX = N_QKV / 32;                     // 96
constexpr int WP_NX = C_ / 32;                        // 32

__global__ void prep_all(const float* __restrict__ x,
                         const float* __restrict__ wa,
                         const float* __restrict__ wp) {
    const int blk = blockIdx.x;
    const int tid = threadIdx.x;
    if (blk < NBX) {
        const size_t i = (size_t)blk * 256 + tid;
        float4 v = ((const float4*)x)[i];
        ((half2*)g_xh)[i * 2 + 0] = __floats2half2_rn(v.x, v.y);
        ((half2*)g_xh)[i * 2 + 1] = __floats2half2_rn(v.z, v.w);
        return;
    }
    __shared__ float tile[32][33];
    const float* in;
    __half* out;
    int n0, k0, N, K;
    if (blk < NBX + NBWA) {
        const int b = blk - NBX;
        in = wa; out = g_wat; N = N_QKV; K = C_;
        n0 = (b % WA_NX) * 32; k0 = (b / WA_NX) * 32;
    } else {
        const int b = blk - NBX - NBWA;
        in = wp; out = g_wpt; N = C_; K = C_;
        n0 = (b % WP_NX) * 32; k0 = (b / WP_NX) * 32;
    }
    const int tx = tid & 31;
    const int ty = tid >> 5; // 0..7
#pragma unroll
    for (int j = 0; j < 4; j++)
        tile[ty + j * 8][tx] = in[(size_t)(k0 + ty + j * 8) * N + n0 + tx];
    __syncthreads();
#pragma unroll
    for (int j = 0; j < 4; j++)
        out[(size_t)(n0 + ty + j * 8) * K + k0 + tx] =
            __float2half_rn(tile[tx][ty + j * 8]);
}

// ---------------------------------------------------------------------------
// Dense fp16 GEMM (R16-passing core): C = A(MxK) * B^T([N][K]) + bias, fp32 acc.
// 128x128x64 tile, 3-stage cp.async, 8 warps (4M x 2N), warp 32x64, ldmatrix.
// MODE 0: fused per-row |q|^2/|k|^2 + vectorized half2 stores for q/k.
// ---------------------------------------------------------------------------
constexpr int BKH = 64;
constexpr int HP = 72;
constexpr int HASZ = 128 * HP;
constexpr int HSTG = 2 * HASZ;
constexpr int GEMM_SMEM = 3 * HSTG * 2;  // 110592 B

template <int MODE>
__global__ __launch_bounds__(256, 2) void gemm_f16(
    const float* __restrict__ bias, float* __restrict__ Cout,
    int M, int N, int K)
{
    extern __shared__ __half smh[];

    const __half* __restrict__ A = (MODE == 0) ? g_xh : g_yh;
    const __half* __restrict__ Bt = (MODE == 0) ? g_wat : g_wpt;

    const int tid = threadIdx.x;
    const int lane = tid & 31;
    const int wid = tid >> 5;
    const int g = lane >> 2;
    const int t4 = lane & 3;
    const int wm = (wid & 3) * 32;
    const int wn = (wid >> 2) * 64;
    const int m0 = blockIdx.y * 128;
    const int n0 = blockIdx.x * 128;
    const int lrow = lane & 15;
    const int lk = (lane >> 4) * 8;

    const int nt = K / BKH;

    auto issue = [&](int stage, int k0) {
        __half* sA = smh + stage * HSTG;
        __half* sB = sA + HASZ;
#pragma unroll
        for (int h = 0; h < 4; h++) {
            int c = tid + h * 256;
            int row = c >> 3, c8 = (c & 7) * 8;
            cp_async16(smem_u32(&sA[row * HP + c8]), &A[(size_t)(m0 + row) * K + k0 + c8]);
            cp_async16(smem_u32(&sB[row * HP + c8]), &Bt[(size_t)(n0 + row) * K + k0 + c8]);
        }
        cp_commit();
    };

    float acc[2][8][4] = {};

    issue(0, 0);
    issue(1, BKH);

    for (int i = 0; i < nt; i++) {
        // Outstanding before wait: {i, i+1} for i<=nt-2, only {i} at tail.
        if (i == nt - 1) cp_wait<0>(); else cp_wait<1>();
        __syncthreads();
        if (i + 2 < nt) issue((i + 2) % 3, (i + 2) * BKH);

        const __half* sA = smh + (i % 3) * HSTG;
        const __half* sB = sA + HASZ;

#pragma unroll
        for (int kk = 0; kk < BKH; kk += 16) {
            uint32_t af[2][4];
#pragma unroll
            for (int mi = 0; mi < 2; mi++)
                ldsm_x4(af[mi][0], af[mi][1], af[mi][2], af[mi][3],
                        smem_u32(&sA[(wm + mi * 16 + lrow) * HP + kk + lk]));
            uint32_t bf[8][2];
#pragma unroll
            for (int nj = 0; nj < 4; nj++)
                ldsm_x4(bf[2 * nj][0], bf[2 * nj + 1][0], bf[2 * nj][1], bf[2 * nj + 1][1],
                        smem_u32(&sB[(wn + nj * 16 + lrow) * HP + kk + lk]));
#pragma unroll
            for (int mi = 0; mi < 2; mi++)
#pragma unroll
                for (int ni = 0; ni < 8; ni++)
                    mma_f16(acc[mi][ni][0], acc[mi][ni][1], acc[mi][ni][2], acc[mi][ni][3],
                            af[mi][0], af[mi][1], af[mi][2], af[mi][3],
                            bf[ni][0], bf[ni][1]);
        }
    }

    // Epilogue (+ fused row-norm reduction for q/k in MODE 0)
    float sq0[2] = {0.0f, 0.0f};
    float sq1[2] = {0.0f, 0.0f};
    const int part = (n0 + wn) >> 10;       // constant per warp
    const int hh = ((n0 + wn) & 1023) >> 6; // head, constant per warp

#pragma unroll
    for (int mi = 0; mi < 2; mi++) {
#pragma unroll
        for (int ni = 0; ni < 8; ni++) {
            const int r0 = m0 + wm + mi * 16 + g;
            const int r1 = r0 + 8;
            const int c0 = n0 + wn + ni * 8 + 2 * t4;
            const float bia = bias[c0];
            const float bib = bias[c0 + 1];
            float v00 = acc[mi][ni][0] + bia;
            float v01 = acc[mi][ni][1] + bib;
            float v10 = acc[mi][ni][2] + bia;
            float v11 = acc[mi][ni][3] + bib;
            if (MODE == 0) {
                const half2 p0 = __floats2half2_rn(v00, v01);
                const half2 p1 = __floats2half2_rn(v10, v11);
                const int d0 = ni * 8 + 2 * t4;
                const int b0i = r0 >> 11, t0i = r0 & 2047;
                const int b1i = r1 >> 11, t1i = r1 & 2047;
                if (part < 2) {
                    const float2 f0 = __half22float2(p0);
                    const float2 f1 = __half22float2(p1);
                    sq0[mi] += f0.x * f0.x + f0.y * f0.y;
                    sq1[mi] += f1.x * f1.x + f1.y * f1.y;
                    __half* dst = (part == 0) ? g_qh : g_kh;
                    *(half2*)&dst[((size_t)(b0i * H_ + hh) * T_ + t0i) * HD + d0] = p0;
                    *(half2*)&dst[((size_t)(b1i * H_ + hh) * T_ + t1i) * HD + d0] = p1;
                } else {
                    g_vt[((size_t)(b0i * H_ + hh) * HD + d0) * T_ + t0i] = __low2half(p0);
                    g_vt[((size_t)(b0i * H_ + hh) * HD + d0 + 1) * T_ + t0i] = __high2half(p0);
                    g_vt[((size_t)(b1i * H_ + hh) * HD + d0) * T_ + t1i] = __low2half(p1);
                    g_vt[((size_t)(b1i * H_ + hh) * HD + d0 + 1) * T_ + t1i] = __high2half(p1);
                }
            } else {
                *(float2*)&Cout[(size_t)r0 * N + c0] = make_float2(v00, v01);
                *(float2*)&Cout[(size_t)r1 * N + c0] = make_float2(v10, v11);
            }
        }
    }

    if (MODE == 0 && part < 2) {
#pragma unroll
        for (int mi = 0; mi < 2; mi++) {
            float s0 = sq0[mi], s1 = sq1[mi];
            s0 += __shfl_xor_sync(0xffffffffu, s0, 1);
            s0 += __shfl_xor_sync(0xffffffffu, s0, 2);
            s1 += __shfl_xor_sync(0xffffffffu, s1, 1);
            s1 += __shfl_xor_sync(0xffffffffu, s1, 2);
            if (t4 == 0) {
                float* dst = (part == 0) ? g_q2 : g_k2;
                const int m0r = m0 + wm + mi * 16 + g;
                {
                    const int b = m0r >> 11, t = m0r & 2047;
                    dst[(b * H_ + hh) * T_ + t] = s0;
                }
                {
                    const int m1r = m0r + 8;
                    const int b = m1r >> 11, t = m1r & 2047;
                    dst[(b * H_ + hh) * T_ + t] = s1;
                }
            }
        }
    }
}

// ---------------------------------------------------------------------------
// Streaming causal Gaussian attention: register-resident S, 8 warps x 16-row
// bands, 3-stage KV ring (2 prefetches in flight), k2 staged via cp.async.
// NEW: Q fragments hoisted into registers once (Q tile is loop-invariant).
// ---------------------------------------------------------------------------
constexpr int QP = 72;
constexpr int Q_OFF = 0;
constexpr int K_OFF = 128 * QP;
constexpr int V_OFF = K_OFF + 3 * 64 * QP;
constexpr int K2_OFF_H = V_OFF + 3 * 64 * QP;        // in halves; float area
constexpr int ATTN_SMEM = K2_OFF_H * 2 + 3 * 64 * 4; // 73728 + 768 B

__global__ __launch_bounds__(256, 2) void attn_f16() {
    extern __shared__ __half smh[];
    __half* Qs = smh + Q_OFF;
    float* k2base = (float*)(smh + K2_OFF_H);

    const int bh = blockIdx.y;
    const int qt = (int)gridDim.x - 1 - (int)blockIdx.x; // longest blocks first
    const int q0 = qt * 128;
    const int tid = threadIdx.x;
    const int lane = tid & 31;
    const int wid = tid >> 5;
    const int g = lane >> 2;
    const int t4 = lane & 3;
    const int wm = wid * 16;
    const int lrow = lane & 15;
    const int lk = (lane >> 4) * 8;

    const __half* __restrict__ qp = g_qh + (size_t)bh * T_ * HD;
    const __half* __restrict__ kp = g_kh + (size_t)bh * T_ * HD;
    const __half* __restrict__ vtp = g_vt + (size_t)bh * HD * T_;

    const int ntile = 2 * qt + 2;

    auto issueKV = [&](int stage, int k0) {
        __half* Ks = smh + K_OFF + stage * 64 * QP;
        __half* Vs = smh + V_OFF + stage * 64 * QP;
#pragma unroll
        for (int h2 = 0; h2 < 2; h2++) {
            int c = tid + h2 * 256;
            int row = c >> 3, cc = (c & 7) * 8;
            cp_async16(smem_u32(&Ks[row * QP + cc]), &kp[(size_t)(k0 + row) * HD + cc]);
            cp_async16(smem_u32(&Vs[row * QP + cc]), &vtp[(size_t)row * T_ + k0 + cc]);
        }
        if (tid < 16)
            cp_async16(smem_u32(&k2base[stage * 64 + tid * 4]),
                       &g_k2[bh * T_ + k0 + tid * 4]);
        cp_commit();
    };

    {
#pragma unroll
        for (int h2 = 0; h2 < 4; h2++) {
            int c = tid + h2 * 256;
            int row = c >> 3, cc = (c & 7) * 8;
            cp_async16(smem_u32(&Qs[row * QP + cc]), &qp[(size_t)(q0 + row) * HD + cc]);
        }
        issueKV(0, 0);
        issueKV(1, 64);
    }

    const float q2a = g_q2[bh * T_ + q0 + wm + g];
    const float q2b = g_q2[bh * T_ + q0 + wm + g + 8];
    const int tq0 = q0 + wm + g;
    const int tq1 = tq0 + 8;

    float yacc[8][4] = {};
    uint32_t qf[4][4]; // hoisted Q fragments (kk = 0,16,32,48)

    for (int jt = 0; jt < ntile; jt++) {
        const int st = jt % 3;
        const int k0 = jt * 64;
        // Outstanding before wait: {jt, jt+1} for jt<=ntile-2, only {jt} at tail.
        if (jt == ntile - 1) cp_wait<0>(); else cp_wait<1>();
        __syncthreads(); // all warps done with tile jt-1 (stage (jt+2)%3)
        if (jt + 2 < ntile) issueKV((jt + 2) % 3, (jt + 2) * 64);

        if (jt == 0) { // Q arrived with group 0; load fragments once
#pragma unroll
            for (int s = 0; s < 4; s++)
                ldsm_x4(qf[s][0], qf[s][1], qf[s][2], qf[s][3],
                        smem_u32(&Qs[(wm + lrow) * QP + 16 * s + lk]));
        }

        const bool full_mask = (k0 > q0 + wm + 15);
        if (full_mask) continue;

        const __half* Ks = smh + K_OFF + st * 64 * QP;
        const __half* Vs = smh + V_OFF + st * 64 * QP;
        const float* k2s = k2base + st * 64;

        // S = Q.K^T  (warp m16 x n64)
        float sacc[8][4] = {};
#pragma unroll
        for (int s = 0; s < 4; s++) {
            uint32_t bf[8][2];
#pragma unroll
            for (int nj = 0; nj < 4; nj++)
                ldsm_x4(bf[2 * nj][0], bf[2 * nj + 1][0], bf[2 * nj][1], bf[2 * nj + 1][1],
                        smem_u32(&Ks[(nj * 16 + lrow) * QP + 16 * s + lk]));
#pragma unroll
            for (int j = 0; j < 8; j++)
                mma_f16(sacc[j][0], sacc[j][1], sacc[j][2], sacc[j][3],
                        qf[s][0], qf[s][1], qf[s][2], qf[s][3], bf[j][0], bf[j][1]);
        }

        // exp + causal mask -> pack directly into SV A-fragments (registers)
        uint32_t sa[4][4];
#pragma unroll
        for (int j = 0; j < 8; j++) {
            const int c0l = j * 8 + 2 * t4;
            const int tk0 = k0 + c0l;
            const int tk1 = tk0 + 1;
            const float2 k2 = *(const float2*)&k2s[c0l];
            float e00 = __expf((q2a + k2.x - 2.0f * sacc[j][0]) * SCALE);
            float e01 = __expf((q2a + k2.y - 2.0f * sacc[j][1]) * SCALE);
            float e10 = __expf((q2b + k2.x - 2.0f * sacc[j][2]) * SCALE);
            float e11 = __expf((q2b + k2.y - 2.0f * sacc[j][3]) * SCALE);
            if (tk0 > tq0) e00 = 0.0f;
            if (tk1 > tq0) e01 = 0.0f;
            if (tk0 > tq1) e10 = 0.0f;
            if (tk1 > tq1) e11 = 0.0f;
            sa[j >> 1][(j & 1) * 2 + 0] = h2u(__floats2half2_rn(e00, e01));
            sa[j >> 1][(j & 1) * 2 + 1] = h2u(__floats2half2_rn(e10, e11));
        }

        // Y += S @ V  (A = register S, B = V^T fragments; k = token)
#pragma unroll
        for (int s = 0; s < 4; s++) {
            uint32_t bf[8][2];
#pragma unroll
            for (int nj = 0; nj < 4; nj++)
                ldsm_x4(bf[2 * nj][0], bf[2 * nj + 1][0], bf[2 * nj][1], bf[2 * nj + 1][1],
                        smem_u32(&Vs[(nj * 16 + lrow) * QP + 16 * s + lk]));
#pragma unroll
            for (int ni = 0; ni < 8; ni++)
                mma_f16(yacc[ni][0], yacc[ni][1], yacc[ni][2], yacc[ni][3],
                        sa[s][0], sa[s][1], sa[s][2], sa[s][3],
                        bf[ni][0], bf[ni][1]);
        }
    }

    // Write Y as fp16 to (B,T,C)
    const int b = bh >> 4;
    const int h = bh & 15;
#pragma unroll
    for (int ni = 0; ni < 8; ni++) {
        const int d = ni * 8 + 2 * t4;
        *(half2*)&g_yh[((size_t)(b * T_ + tq0)) * C_ + h * HD + d] =
            __floats2half2_rn(yacc[ni][0], yacc[ni][1]);
        *(half2*)&g_yh[((size_t)(b * T_ + tq1)) * C_ + h * HD + d] =
            __floats2half2_rn(yacc[ni][2], yacc[ni][3]);
    }
}

// ---------------------------------------------------------------------------
extern "C" void kernel_launch(void* const* d_in, const int* in_sizes, int n_in,
                              void* d_out, int out_size) {
    (void)in_sizes; (void)n_in; (void)out_size;
    const float* x      = (const float*)d_in[0];
    const float* W_attn = (const float*)d_in[1];
    const float* b_attn = (const float*)d_in[2];
    const float* W_proj = (const float*)d_in[3];
    const float* b_proj = (const float*)d_in[4];
    float* out = (float*)d_out;

    cudaFuncSetAttribute(gemm_f16<0>, cudaFuncAttributeMaxDynamicSharedMemorySize, GEMM_SMEM);
    cudaFuncSetAttribute(gemm_f16<1>, cudaFuncAttributeMaxDynamicSharedMemorySize, GEMM_SMEM);
    cudaFuncSetAttribute(attn_f16, cudaFuncAttributeMaxDynamicSharedMemorySize, ATTN_SMEM);

    prep_all<<<NBX + NBWA + NBWP, 256>>>(x, W_attn, W_proj);

    dim3 g1(N_QKV / 128, M_ROWS / 128);
    gemm_f16<0><<<g1, 256, GEMM_SMEM>>>(b_attn, nullptr, M_ROWS, N_QKV, C_);

    attn_f16<<<dim3(T_ / 128, BH), 256, ATTN_SMEM>>>();

    dim3 g2(C_ / 128, M_ROWS / 128);
    gemm_f16<1><<<g2, 256, GEMM_SMEM>>>(b_proj, out, M_ROWS, C_, C_);
}